// round 8
// baseline (speedup 1.0000x reference)
#include <cuda_runtime.h>
#include <cuda_bf16.h>
#include <cstdint>

#define VOCAB  8000
#define HIDDEN 256
#define BATCH  32
#define SEQ    256
#define OUT_MAIN (SEQ * BATCH * VOCAB)   // 65,536,000 floats

typedef unsigned long long ull;

// ---------------- scratch (__device__ globals: no allocs allowed) ----------
__device__ __align__(16) __nv_bfloat16 g_Y0[SEQ * BATCH * HIDDEN];  // bf16 hi of Y
__device__ __align__(16) __nv_bfloat16 g_Y1[SEQ * BATCH * HIDDEN];  // bf16 residual
__device__ __align__(16) __nv_bfloat16 g_W0[VOCAB * HIDDEN];        // bf16 hi of W_out
__device__ __align__(16) __nv_bfloat16 g_W1[VOCAB * HIDDEN];        // bf16 residual

// ---------------- small PTX helpers ---------------------------------------
__device__ __forceinline__ void ffma2(ull& d, ull a, ull b) {
    asm("fma.rn.f32x2 %0, %1, %2, %0;" : "+l"(d) : "l"(a), "l"(b));
}
__device__ __forceinline__ float2 unpack2(ull v) {
    float2 r; asm("mov.b64 {%0, %1}, %2;" : "=f"(r.x), "=f"(r.y) : "l"(v)); return r;
}
union F4U { float4 f4; ulonglong2 u2; };

__device__ __forceinline__ uint32_t smem_u32(const void* p) {
    uint32_t a;
    asm("{ .reg .u64 t; cvta.to.shared.u64 t, %1; cvt.u32.u64 %0, t; }" : "=r"(a) : "l"(p));
    return a;
}
__device__ __forceinline__ void ldsm4(uint32_t* r, uint32_t addr) {
    asm volatile("ldmatrix.sync.aligned.m8n8.x4.shared.b16 {%0,%1,%2,%3}, [%4];"
                 : "=r"(r[0]), "=r"(r[1]), "=r"(r[2]), "=r"(r[3]) : "r"(addr));
}
__device__ __forceinline__ void mma16816(float* c, const uint32_t* a,
                                         uint32_t b0, uint32_t b1) {
    asm volatile(
        "mma.sync.aligned.m16n8k16.row.col.f32.bf16.bf16.f32 "
        "{%0,%1,%2,%3}, {%4,%5,%6,%7}, {%8,%9}, {%0,%1,%2,%3};"
        : "+f"(c[0]), "+f"(c[1]), "+f"(c[2]), "+f"(c[3])
        : "r"(a[0]), "r"(a[1]), "r"(a[2]), "r"(a[3]), "r"(b0), "r"(b1));
}

// ---------------- prep: W_out -> bf16 hi/lo --------------------------------
__global__ void prep_w_kernel(const float* __restrict__ W_out) {
    int i = blockIdx.x * blockDim.x + threadIdx.x;
    if (i < VOCAB * HIDDEN) {
        float w = W_out[i];
        __nv_bfloat16 w0 = __float2bfloat16(w);
        g_W0[i] = w0;
        g_W1[i] = __float2bfloat16(w - __bfloat162float(w0));
    }
}

// ---------------- recurrence: 2-CTA cluster, W_hh register-resident --------
// mbarrier handshake instead of barrier.cluster: one mbar per CTA, 256
// arrivals per phase (128 local s==0 + 128 peer s==0). Double-buffered h.
__global__ __launch_bounds__(512, 1) __cluster_dims__(2, 1, 1)
void rnn_kernel(
    const int*   __restrict__ X,
    const float* __restrict__ h0,
    const float* __restrict__ W_ih,
    const float* __restrict__ b_ih,
    const float* __restrict__ W_hh,
    const float* __restrict__ b_hh,
    float*       __restrict__ hlast,
    int write_hlast)
{
    __shared__ __align__(16) float h_sh[2][HIDDEN];
    __shared__ float psum[4][128];
    __shared__ int   x_sh[SEQ];
    __shared__ __align__(8) ull mbar;

    const int cta  = blockIdx.x;
    const int b    = cta >> 1;
    const int rank = cta & 1;
    const int tid  = threadIdx.x;
    const int jl   = tid & 127;        // local output row
    const int s    = tid >> 7;         // k-slice 0..3
    const int jg   = rank * 128 + jl;  // global output row

    // W_hh rows into registers (one-time, ~128KB per CTA)
    F4U w[16];
    const float4* wrow =
        reinterpret_cast<const float4*>(W_hh + (size_t)jg * HIDDEN + s * 64);
    #pragma unroll
    for (int i = 0; i < 16; ++i) w[i].f4 = wrow[i];

    float bias = 0.f;
    if (s == 0) bias = b_hh[jg] + b_ih[jg];
    if (tid < HIDDEN) h_sh[0][tid] = h0[b * HIDDEN + tid];
    if (tid < SEQ)    x_sh[tid]    = X[b * SEQ + tid];

    const uint32_t local_mbar = smem_u32(&mbar);
    const uint32_t local_h    = smem_u32(&h_sh[0][0]);
    uint32_t remote_mbar, remote_h;
    asm("mapa.shared::cluster.u32 %0, %1, %2;"
        : "=r"(remote_mbar) : "r"(local_mbar), "r"(rank ^ 1));
    asm("mapa.shared::cluster.u32 %0, %1, %2;"
        : "=r"(remote_h) : "r"(local_h), "r"(rank ^ 1));

    if (tid == 0)
        asm volatile("mbarrier.init.shared.b64 [%0], %1;"
                     :: "r"(local_mbar), "r"(256) : "memory");
    __syncthreads();
    // one-time cluster barrier: peer mbar init + h0 visible before step 0
    asm volatile("barrier.cluster.arrive.aligned;" ::: "memory");
    asm volatile("barrier.cluster.wait.aligned;"   ::: "memory");

    const float* Wih_row = W_ih + (size_t)jg * VOCAB;

    #pragma unroll 1
    for (int t = 0; t < SEQ; ++t) {
        const int cur = t & 1, nxt = cur ^ 1;

        // embedding gather prefetch (L2-latency hidden by fma loop + sync)
        float xv = 0.f;
        if (s == 0) xv = __ldg(&Wih_row[x_sh[t]]);

        ull a0 = 0ULL, a1 = 0ULL;
        const ulonglong2* h2 =
            reinterpret_cast<const ulonglong2*>(&h_sh[cur][s * 64]);
        #pragma unroll
        for (int i = 0; i < 16; i += 2) {
            ulonglong2 hva = h2[i];        // broadcast LDS.128
            ffma2(a0, hva.x, w[i].u2.x);
            ffma2(a0, hva.y, w[i].u2.y);
            ulonglong2 hvb = h2[i + 1];
            ffma2(a1, hvb.x, w[i + 1].u2.x);
            ffma2(a1, hvb.y, w[i + 1].u2.y);
        }
        float2 p0 = unpack2(a0), p1 = unpack2(a1);
        psum[s][jl] = (p0.x + p0.y) + (p1.x + p1.y);
        __syncthreads();

        if (s == 0) {
            float v = psum[0][jl] + psum[1][jl] + psum[2][jl] + psum[3][jl]
                    + xv + bias;
            float hn = tanhf(v);
            h_sh[nxt][jg] = hn;
            uint32_t raddr = remote_h + (uint32_t)((nxt * HIDDEN + jg) * 4);
            asm volatile("st.shared::cluster.f32 [%0], %1;"
                         :: "r"(raddr), "f"(hn) : "memory");
            asm volatile("mbarrier.arrive.release.cluster.shared::cta.b64 _, [%0];"
                         :: "r"(local_mbar) : "memory");
            asm volatile("mbarrier.arrive.release.cluster.shared::cluster.b64 _, [%0];"
                         :: "r"(remote_mbar) : "memory");
            // Y stores off the critical path
            size_t idx = (size_t)(t * BATCH + b) * HIDDEN + jg;
            __nv_bfloat16 y0 = __float2bfloat16(hn);
            g_Y0[idx] = y0;
            g_Y1[idx] = __float2bfloat16(hn - __bfloat162float(y0));
        }
        // wait for phase t (256 arrivals): both h halves of buffer nxt ready
        {
            const uint32_t par = (uint32_t)(t & 1);
            asm volatile(
                "{\n\t.reg .pred P1;\n\t"
                "W_%=:\n\t"
                "mbarrier.try_wait.parity.acquire.cluster.shared::cta.b64 P1, [%0], %1, 0x989680;\n\t"
                "@P1 bra.uni D_%=;\n\t"
                "bra.uni W_%=;\n\t"
                "D_%=:\n\t}" :: "r"(local_mbar), "r"(par) : "memory");
        }
    }

    if (write_hlast && s == 0)
        hlast[b * HIDDEN + jg] = h_sh[0][jg];   // SEQ even -> final h in buf 0
}

// ---------------- HMMA GEMM: C = Y @ W_out^T + b_out ----------------------
// mma.sync m16n8k16 bf16, 3-term split: D = a0b0 + a1b0 + a0b1 (fp32 accum).
// Pass order caches a0 and b0 in regs: 12 ldsm per k-step instead of 14.
#define BM 128
#define BN 128
#define BK 32
#define ASTR2 40   // smem row stride in bf16 (80B: ldmatrix-conflict-free)
#define NTILES ((VOCAB + BN - 1) / BN)   // 63

__shared__ __nv_bfloat16 sA0[BM * ASTR2];
__shared__ __nv_bfloat16 sA1[BM * ASTR2];
__shared__ __nv_bfloat16 sB0[BN * ASTR2];
__shared__ __nv_bfloat16 sB1[BN * ASTR2];

__device__ __forceinline__ void load_block(__nv_bfloat16* dst,
    const __nv_bfloat16* src, int row0, int rowmax, int kc, int tid)
{
    const uint4* s = reinterpret_cast<const uint4*>(src);
    #pragma unroll
    for (int p = 0; p < 2; ++p) {
        int q = tid + p * 256;
        int r = q >> 2, f = q & 3;               // r: tile row, f: 16B chunk
        int grow = row0 + r; if (grow > rowmax) grow = rowmax;
        uint4 v = s[(size_t)grow * (HIDDEN / 8) + (kc >> 3) + f];
        *reinterpret_cast<uint4*>(dst + r * ASTR2 + f * 8) = v;
    }
}

__global__ __launch_bounds__(256, 2) void gemm_kernel(
    const float* __restrict__ b_out,
    float*       __restrict__ C)
{
    const int tid  = threadIdx.x;
    const int lane = tid & 31;
    const int wid  = tid >> 5;
    const int wm   = wid & 1;        // 2 M-slices of 64
    const int wn   = wid >> 1;       // 4 N-slices of 32
    const int rb   = blockIdx.y * BM;
    const int cb   = blockIdx.x * BN;

    const uint32_t a0b = smem_u32(sA0), a1b = smem_u32(sA1);
    const uint32_t b0b = smem_u32(sB0), b1b = smem_u32(sB1);

    // per-lane ldmatrix address components
    const int arow = wm * 64 + (lane & 15);          // + ma*16
    const int acol = (lane >> 4) << 3;               // + kk
    const int brow = wn * 32 + (lane & 7) + ((lane >> 4) << 3);  // + pair*16
    const int bcol = ((lane >> 3) & 1) << 3;         // + kk

    float c[4][4][4];
    #pragma unroll
    for (int i = 0; i < 4; ++i)
        #pragma unroll
        for (int j = 0; j < 4; ++j)
            #pragma unroll
            for (int k = 0; k < 4; ++k) c[i][j][k] = 0.f;

    #pragma unroll 1
    for (int kc = 0; kc < HIDDEN; kc += BK) {
        load_block(sA0, g_Y0, rb, SEQ * BATCH - 1, kc, tid);
        load_block(sA1, g_Y1, rb, SEQ * BATCH - 1, kc, tid);
        load_block(sB0, g_W0, cb, VOCAB - 1, kc, tid);
        load_block(sB1, g_W1, cb, VOCAB - 1, kc, tid);
        __syncthreads();

        #pragma unroll
        for (int ks = 0; ks < 2; ++ks) {
            const int kk = ks * 16;
            const uint32_t aoff = (uint32_t)((arow * ASTR2 + kk + acol) * 2);
            const uint32_t boff = (uint32_t)((brow * ASTR2 + kk + bcol) * 2);

            uint32_t af0[4][4], af1[4][4], bf[2][4];

            // load a0, b0
            #pragma unroll
            for (int ma = 0; ma < 4; ++ma)
                ldsm4(af0[ma], a0b + aoff + (uint32_t)(ma * 16 * ASTR2 * 2));
            #pragma unroll
            for (int p = 0; p < 2; ++p)
                ldsm4(bf[p], b0b + boff + (uint32_t)(p * 16 * ASTR2 * 2));

            // pass 1: a0 * b0
            #pragma unroll
            for (int ma = 0; ma < 4; ++ma)
                #pragma unroll
                for (int nb = 0; nb < 4; ++nb)
                    mma16816(c[ma][nb], af0[ma],
                             bf[nb >> 1][(nb & 1) * 2], bf[nb >> 1][(nb & 1) * 2 + 1]);

            // load a1; pass 2: a1 * b0 (b0 cached)
            #pragma unroll
            for (int ma = 0; ma < 4; ++ma)
                ldsm4(af1[ma], a1b + aoff + (uint32_t)(ma * 16 * ASTR2 * 2));
            #pragma unroll
            for (int ma = 0; ma < 4; ++ma)
                #pragma unroll
                for (int nb = 0; nb < 4; ++nb)
                    mma16816(c[ma][nb], af1[ma],
                             bf[nb >> 1][(nb & 1) * 2], bf[nb >> 1][(nb & 1) * 2 + 1]);

            // load b1 (overwrite b0); pass 3: a0 * b1 (a0 cached)
            #pragma unroll
            for (int p = 0; p < 2; ++p)
                ldsm4(bf[p], b1b + boff + (uint32_t)(p * 16 * ASTR2 * 2));
            #pragma unroll
            for (int ma = 0; ma < 4; ++ma)
                #pragma unroll
                for (int nb = 0; nb < 4; ++nb)
                    mma16816(c[ma][nb], af0[ma],
                             bf[nb >> 1][(nb & 1) * 2], bf[nb >> 1][(nb & 1) * 2 + 1]);
        }
        __syncthreads();
    }

    // Epilogue: direct float2 stores + bias
    const int g = lane >> 2, t4 = lane & 3;
    #pragma unroll
    for (int nb = 0; nb < 4; ++nb) {
        int col = cb + wn * 32 + nb * 8 + 2 * t4;
        if (col >= VOCAB) continue;
        float bx = __ldg(&b_out[col]);
        float by = __ldg(&b_out[col + 1]);
        #pragma unroll
        for (int ma = 0; ma < 4; ++ma) {
            int row = rb + wm * 64 + ma * 16 + g;
            float2 v0 = make_float2(c[ma][nb][0] + bx, c[ma][nb][1] + by);
            float2 v1 = make_float2(c[ma][nb][2] + bx, c[ma][nb][3] + by);
            *reinterpret_cast<float2*>(&C[(size_t)row * VOCAB + col])       = v0;
            *reinterpret_cast<float2*>(&C[(size_t)(row + 8) * VOCAB + col]) = v1;
        }
    }
}

// ---------------- launch ---------------------------------------------------
extern "C" void kernel_launch(void* const* d_in, const int* in_sizes, int n_in,
                              void* d_out, int out_size)
{
    const int*   X     = (const int*)  d_in[0];
    const float* h0    = (const float*)d_in[1];
    const float* W_ih  = (const float*)d_in[2];
    const float* b_ih  = (const float*)d_in[3];
    const float* W_hh  = (const float*)d_in[4];
    const float* b_hh  = (const float*)d_in[5];
    const float* W_out = (const float*)d_in[6];
    const float* b_out = (const float*)d_in[7];
    float* out = (float*)d_out;

    int write_hlast = (out_size >= OUT_MAIN + BATCH * HIDDEN) ? 1 : 0;
    float* hlast = out + OUT_MAIN;

    prep_w_kernel<<<(VOCAB * HIDDEN + 1023) / 1024, 1024>>>(W_out);
    rnn_kernel<<<BATCH * 2, 512>>>(X, h0, W_ih, b_ih, W_hh, b_hh,
                                   hlast, write_hlast);
    gemm_kernel<<<dim3(NTILES, (SEQ * BATCH) / BM), 256>>>(b_out, out);
}

// round 9
// speedup vs baseline: 1.0710x; 1.0710x over previous
#include <cuda_runtime.h>
#include <cuda_bf16.h>
#include <cstdint>

#define VOCAB  8000
#define HIDDEN 256
#define BATCH  32
#define SEQ    256
#define OUT_MAIN (SEQ * BATCH * VOCAB)   // 65,536,000 floats

typedef unsigned long long ull;

// ---------------- scratch (__device__ globals: no allocs allowed) ----------
__device__ __align__(16) __nv_bfloat16 g_Y0[SEQ * BATCH * HIDDEN];  // bf16 hi of Y
__device__ __align__(16) __nv_bfloat16 g_Y1[SEQ * BATCH * HIDDEN];  // bf16 residual
__device__ __align__(16) __nv_bfloat16 g_W0[VOCAB * HIDDEN];        // bf16 hi of W_out
__device__ __align__(16) __nv_bfloat16 g_W1[VOCAB * HIDDEN];        // bf16 residual

// ---------------- small PTX helpers ---------------------------------------
__device__ __forceinline__ void ffma2(ull& d, ull a, ull b) {
    asm("fma.rn.f32x2 %0, %1, %2, %0;" : "+l"(d) : "l"(a), "l"(b));
}
__device__ __forceinline__ float2 unpack2(ull v) {
    float2 r; asm("mov.b64 {%0, %1}, %2;" : "=f"(r.x), "=f"(r.y) : "l"(v)); return r;
}
union F4U { float4 f4; ulonglong2 u2; };

__device__ __forceinline__ uint32_t smem_u32(const void* p) {
    uint32_t a;
    asm("{ .reg .u64 t; cvta.to.shared.u64 t, %1; cvt.u32.u64 %0, t; }" : "=r"(a) : "l"(p));
    return a;
}
__device__ __forceinline__ void ldsm4(uint32_t* r, uint32_t addr) {
    asm volatile("ldmatrix.sync.aligned.m8n8.x4.shared.b16 {%0,%1,%2,%3}, [%4];"
                 : "=r"(r[0]), "=r"(r[1]), "=r"(r[2]), "=r"(r[3]) : "r"(addr));
}
__device__ __forceinline__ void mma16816(float* c, const uint32_t* a,
                                         uint32_t b0, uint32_t b1) {
    asm volatile(
        "mma.sync.aligned.m16n8k16.row.col.f32.bf16.bf16.f32 "
        "{%0,%1,%2,%3}, {%4,%5,%6,%7}, {%8,%9}, {%0,%1,%2,%3};"
        : "+f"(c[0]), "+f"(c[1]), "+f"(c[2]), "+f"(c[3])
        : "r"(a[0]), "r"(a[1]), "r"(a[2]), "r"(a[3]), "r"(b0), "r"(b1));
}

// ---------------- prep: W_out -> bf16 hi/lo --------------------------------
__global__ void prep_w_kernel(const float* __restrict__ W_out) {
    int i = blockIdx.x * blockDim.x + threadIdx.x;
    if (i < VOCAB * HIDDEN) {
        float w = W_out[i];
        __nv_bfloat16 w0 = __float2bfloat16(w);
        g_W0[i] = w0;
        g_W1[i] = __float2bfloat16(w - __bfloat162float(w0));
    }
}

// ---------------- recurrence: 2-CTA cluster, W_hh register-resident --------
// Warp-local reduction (shfl) + 16-arrival mbarrier handshake.
// warp w, lane l: row jl = w*8 + (l&7), k-slice s = l>>3 (64 regs of W_hh).
// h_sh slices padded to stride 68 floats (conflict-free 4-way broadcast).
#define HSTR 68

__global__ __launch_bounds__(512, 1) __cluster_dims__(2, 1, 1)
void rnn_kernel(
    const int*   __restrict__ X,
    const float* __restrict__ h0,
    const float* __restrict__ W_ih,
    const float* __restrict__ b_ih,
    const float* __restrict__ W_hh,
    const float* __restrict__ b_hh,
    float*       __restrict__ hlast,
    int write_hlast)
{
    __shared__ __align__(16) float h_sh[2][4 * HSTR];
    __shared__ int  x_sh[SEQ];
    __shared__ __align__(8) ull mbar;

    const int cta  = blockIdx.x;
    const int b    = cta >> 1;
    const int rank = cta & 1;
    const int tid  = threadIdx.x;
    const int wrp  = tid >> 5;
    const int l    = tid & 31;
    const int jl   = wrp * 8 + (l & 7);   // local output row 0..127
    const int s    = l >> 3;              // k-slice 0..3
    const int jg   = rank * 128 + jl;     // global output row

    // W_hh[jg, s*64 .. s*64+63] into registers
    F4U w[16];
    const float4* wrow =
        reinterpret_cast<const float4*>(W_hh + (size_t)jg * HIDDEN + s * 64);
    #pragma unroll
    for (int i = 0; i < 16; ++i) w[i].f4 = wrow[i];

    float bias = 0.f;
    if (l < 8) bias = b_hh[jg] + b_ih[jg];

    if (tid < HIDDEN)
        h_sh[0][(tid >> 6) * HSTR + (tid & 63)] = h0[b * HIDDEN + tid];
    if (tid < SEQ) x_sh[tid] = X[b * SEQ + tid];

    const uint32_t local_mbar = smem_u32(&mbar);
    const uint32_t local_h    = smem_u32(&h_sh[0][0]);
    uint32_t remote_mbar, remote_h;
    asm("mapa.shared::cluster.u32 %0, %1, %2;"
        : "=r"(remote_mbar) : "r"(local_mbar), "r"(rank ^ 1));
    asm("mapa.shared::cluster.u32 %0, %1, %2;"
        : "=r"(remote_h) : "r"(local_h), "r"(rank ^ 1));

    if (tid == 0)
        asm volatile("mbarrier.init.shared.b64 [%0], %1;"
                     :: "r"(local_mbar), "r"(32) : "memory");
    __syncthreads();
    // one-time cluster barrier: peer mbar init visible before first arrives
    asm volatile("barrier.cluster.arrive.aligned;" ::: "memory");
    asm volatile("barrier.cluster.wait.aligned;"   ::: "memory");

    const float* Wih_row = W_ih + (size_t)jg * VOCAB;
    const uint32_t hoff = (uint32_t)((jg >> 6) * HSTR + (jg & 63)) * 4u;
    float last_hn = 0.f;

    #pragma unroll 1
    for (int t = 0; t < SEQ; ++t) {
        const int cur = t & 1, nxt = cur ^ 1;

        // embedding gather prefetch (L2-latency hidden by fma loop)
        float xv = 0.f;
        if (l < 8) xv = __ldg(&Wih_row[x_sh[t]]);

        ull a0 = 0ULL, a1 = 0ULL;
        const ulonglong2* h2 =
            reinterpret_cast<const ulonglong2*>(&h_sh[cur][s * HSTR]);
        #pragma unroll
        for (int i = 0; i < 16; i += 2) {
            ulonglong2 hva = h2[i];        // broadcast LDS.128, conflict-free
            ffma2(a0, hva.x, w[i].u2.x);
            ffma2(a0, hva.y, w[i].u2.y);
            ulonglong2 hvb = h2[i + 1];
            ffma2(a1, hvb.x, w[i + 1].u2.x);
            ffma2(a1, hvb.y, w[i + 1].u2.y);
        }
        float2 p0 = unpack2(a0), p1 = unpack2(a1);
        float part = (p0.x + p0.y) + (p1.x + p1.y);
        part += __shfl_down_sync(0xffffffffu, part, 16);
        part += __shfl_down_sync(0xffffffffu, part, 8);

        float hn = 0.f;
        if (l < 8) {
            hn = tanhf(part + xv + bias);
            last_hn = hn;
            h_sh[nxt][(jg >> 6) * HSTR + (jg & 63)] = hn;
            uint32_t raddr = remote_h
                           + (uint32_t)(nxt * 4 * HSTR * 4) + hoff;
            asm volatile("st.shared::cluster.f32 [%0], %1;"
                         :: "r"(raddr), "f"(hn) : "memory");
        }
        __syncwarp();
        if (l == 0) {
            asm volatile("mbarrier.arrive.release.cta.shared::cta.b64 _, [%0];"
                         :: "r"(local_mbar) : "memory");
            asm volatile("mbarrier.arrive.release.cluster.shared::cluster.b64 _, [%0];"
                         :: "r"(remote_mbar) : "memory");
        }
        if (l < 8) {
            // Y stores off the sync critical path
            size_t idx = (size_t)(t * BATCH + b) * HIDDEN + jg;
            __nv_bfloat16 y0 = __float2bfloat16(hn);
            g_Y0[idx] = y0;
            g_Y1[idx] = __float2bfloat16(hn - __bfloat162float(y0));
        }
        // wait for phase t: 32 arrivals (16 own warps + 16 peer warps)
        {
            const uint32_t par = (uint32_t)(t & 1);
            asm volatile(
                "{\n\t.reg .pred P1;\n\t"
                "W_%=:\n\t"
                "mbarrier.try_wait.parity.acquire.cluster.shared::cta.b64 P1, [%0], %1, 0x989680;\n\t"
                "@P1 bra.uni D_%=;\n\t"
                "bra.uni W_%=;\n\t"
                "D_%=:\n\t}" :: "r"(local_mbar), "r"(par) : "memory");
        }
    }

    if (write_hlast && l < 8)
        hlast[b * HIDDEN + jg] = last_hn;
}

// ---------------- HMMA GEMM: C = Y @ W_out^T + b_out ----------------------
// (reverted to the R6/R7 version measured at 310us; 14 ldsm / k-step)
#define BM 128
#define BN 128
#define BK 32
#define ASTR2 40   // smem row stride in bf16 (80B: ldmatrix-conflict-free)
#define NTILES ((VOCAB + BN - 1) / BN)   // 63

__shared__ __nv_bfloat16 sA0[BM * ASTR2];
__shared__ __nv_bfloat16 sA1[BM * ASTR2];
__shared__ __nv_bfloat16 sB0[BN * ASTR2];
__shared__ __nv_bfloat16 sB1[BN * ASTR2];

__device__ __forceinline__ void load_block(__nv_bfloat16* dst,
    const __nv_bfloat16* src, int row0, int rowmax, int kc, int tid)
{
    const uint4* s = reinterpret_cast<const uint4*>(src);
    #pragma unroll
    for (int p = 0; p < 2; ++p) {
        int q = tid + p * 256;
        int r = q >> 2, f = q & 3;               // r: tile row, f: 16B chunk
        int grow = row0 + r; if (grow > rowmax) grow = rowmax;
        uint4 v = s[(size_t)grow * (HIDDEN / 8) + (kc >> 3) + f];
        *reinterpret_cast<uint4*>(dst + r * ASTR2 + f * 8) = v;
    }
}

__global__ __launch_bounds__(256, 2) void gemm_kernel(
    const float* __restrict__ b_out,
    float*       __restrict__ C)
{
    const int tid  = threadIdx.x;
    const int lane = tid & 31;
    const int wid  = tid >> 5;
    const int wm   = wid & 1;        // 2 M-slices of 64
    const int wn   = wid >> 1;       // 4 N-slices of 32
    const int rb   = blockIdx.y * BM;
    const int cb   = blockIdx.x * BN;

    const uint32_t a0b = smem_u32(sA0), a1b = smem_u32(sA1);
    const uint32_t b0b = smem_u32(sB0), b1b = smem_u32(sB1);

    const int arow = wm * 64 + (lane & 15);
    const int acol = (lane >> 4) << 3;
    const int brow = wn * 32 + (lane & 7) + ((lane >> 4) << 3);
    const int bcol = ((lane >> 3) & 1) << 3;

    float c[4][4][4];
    #pragma unroll
    for (int i = 0; i < 4; ++i)
        #pragma unroll
        for (int j = 0; j < 4; ++j)
            #pragma unroll
            for (int k = 0; k < 4; ++k) c[i][j][k] = 0.f;

    #pragma unroll 1
    for (int kc = 0; kc < HIDDEN; kc += BK) {
        load_block(sA0, g_Y0, rb, SEQ * BATCH - 1, kc, tid);
        load_block(sA1, g_Y1, rb, SEQ * BATCH - 1, kc, tid);
        load_block(sB0, g_W0, cb, VOCAB - 1, kc, tid);
        load_block(sB1, g_W1, cb, VOCAB - 1, kc, tid);
        __syncthreads();

        #pragma unroll
        for (int ks = 0; ks < 2; ++ks) {
            const int kk = ks * 16;
            const uint32_t aoff = (uint32_t)((arow * ASTR2 + kk + acol) * 2);
            const uint32_t boff = (uint32_t)((brow * ASTR2 + kk + bcol) * 2);

            uint32_t af[4][4], bf[2][4];
            #pragma unroll
            for (int ma = 0; ma < 4; ++ma)
                ldsm4(af[ma], a0b + aoff + (uint32_t)(ma * 16 * ASTR2 * 2));
            #pragma unroll
            for (int p = 0; p < 2; ++p)
                ldsm4(bf[p], b0b + boff + (uint32_t)(p * 16 * ASTR2 * 2));

            // pass 1: a0 * b0
            #pragma unroll
            for (int ma = 0; ma < 4; ++ma)
                #pragma unroll
                for (int nb = 0; nb < 4; ++nb)
                    mma16816(c[ma][nb], af[ma],
                             bf[nb >> 1][(nb & 1) * 2], bf[nb >> 1][(nb & 1) * 2 + 1]);

            // pass 2: a0 * b1
            #pragma unroll
            for (int p = 0; p < 2; ++p)
                ldsm4(bf[p], b1b + boff + (uint32_t)(p * 16 * ASTR2 * 2));
            #pragma unroll
            for (int ma = 0; ma < 4; ++ma)
                #pragma unroll
                for (int nb = 0; nb < 4; ++nb)
                    mma16816(c[ma][nb], af[ma],
                             bf[nb >> 1][(nb & 1) * 2], bf[nb >> 1][(nb & 1) * 2 + 1]);

            // pass 3: a1 * b0
            #pragma unroll
            for (int ma = 0; ma < 4; ++ma)
                ldsm4(af[ma], a1b + aoff + (uint32_t)(ma * 16 * ASTR2 * 2));
            #pragma unroll
            for (int p = 0; p < 2; ++p)
                ldsm4(bf[p], b0b + boff + (uint32_t)(p * 16 * ASTR2 * 2));
            #pragma unroll
            for (int ma = 0; ma < 4; ++ma)
                #pragma unroll
                for (int nb = 0; nb < 4; ++nb)
                    mma16816(c[ma][nb], af[ma],
                             bf[nb >> 1][(nb & 1) * 2], bf[nb >> 1][(nb & 1) * 2 + 1]);
        }
        __syncthreads();
    }

    const int g = lane >> 2, t4 = lane & 3;
    #pragma unroll
    for (int nb = 0; nb < 4; ++nb) {
        int col = cb + wn * 32 + nb * 8 + 2 * t4;
        if (col >= VOCAB) continue;
        float bx = __ldg(&b_out[col]);
        float by = __ldg(&b_out[col + 1]);
        #pragma unroll
        for (int ma = 0; ma < 4; ++ma) {
            int row = rb + wm * 64 + ma * 16 + g;
            float2 v0 = make_float2(c[ma][nb][0] + bx, c[ma][nb][1] + by);
            float2 v1 = make_float2(c[ma][nb][2] + bx, c[ma][nb][3] + by);
            *reinterpret_cast<float2*>(&C[(size_t)row * VOCAB + col])       = v0;
            *reinterpret_cast<float2*>(&C[(size_t)(row + 8) * VOCAB + col]) = v1;
        }
    }
}

// ---------------- launch ---------------------------------------------------
extern "C" void kernel_launch(void* const* d_in, const int* in_sizes, int n_in,
                              void* d_out, int out_size)
{
    const int*   X     = (const int*)  d_in[0];
    const float* h0    = (const float*)d_in[1];
    const float* W_ih  = (const float*)d_in[2];
    const float* b_ih  = (const float*)d_in[3];
    const float* W_hh  = (const float*)d_in[4];
    const float* b_hh  = (const float*)d_in[5];
    const float* W_out = (const float*)d_in[6];
    const float* b_out = (const float*)d_in[7];
    float* out = (float*)d_out;

    int write_hlast = (out_size >= OUT_MAIN + BATCH * HIDDEN) ? 1 : 0;
    float* hlast = out + OUT_MAIN;

    prep_w_kernel<<<(VOCAB * HIDDEN + 1023) / 1024, 1024>>>(W_out);
    rnn_kernel<<<BATCH * 2, 512>>>(X, h0, W_ih, b_ih, W_hh, b_hh,
                                   hlast, write_hlast);
    gemm_kernel<<<dim3(NTILES, (SEQ * BATCH) / BM), 256>>>(b_out, out);
}